// round 1
// baseline (speedup 1.0000x reference)
#include <cuda_runtime.h>
#include <math.h>

#define T_  1024
#define C_  1024
#define H_  16
#define HD_ 64
#define B_  4
#define C3_ 3072

// Scratch (device globals: allocation-free per harness rules)
__device__ float g_qkv[(size_t)B_ * T_ * C3_];   // (B*T, 3C) = qkv projection output
__device__ float g_y[(size_t)B_ * T_ * C_];      // (B*T, C)  = attention output pre-proj

// ---------------------------------------------------------------------------
// 128x128x16 register-blocked SGEMM with bias: C = A @ B + bias
// A: (M,K) row-major, B: (K,N) row-major, bias: (N)
// 256 threads, 8x8 micro-tile per thread. All dims divisible by tiles here.
// ---------------------------------------------------------------------------
__global__ __launch_bounds__(256, 2)
void gemm_bias_kernel(const float* __restrict__ A, const float* __restrict__ Bw,
                      const float* __restrict__ bias, float* __restrict__ Cm,
                      int M, int N, int K)
{
    __shared__ float As[16][132];
    __shared__ float Bs[16][132];
    const int tid = threadIdx.x;
    const int tx = tid & 15, ty = tid >> 4;
    const int m0 = blockIdx.y * 128, n0 = blockIdx.x * 128;

    float acc[8][8];
#pragma unroll
    for (int a = 0; a < 8; ++a)
#pragma unroll
        for (int b = 0; b < 8; ++b) acc[a][b] = 0.f;

    for (int k0 = 0; k0 < K; k0 += 16) {
        // Load A tile (128 x 16), store transposed As[k][m]
#pragma unroll
        for (int u = 0; u < 2; ++u) {
            int idx = u * 256 + tid;          // 0..511
            int row = idx >> 2, c4 = idx & 3; // row 0..127, c4 0..3
            float4 v = *(const float4*)&A[(size_t)(m0 + row) * K + k0 + c4 * 4];
            As[c4 * 4 + 0][row] = v.x;
            As[c4 * 4 + 1][row] = v.y;
            As[c4 * 4 + 2][row] = v.z;
            As[c4 * 4 + 3][row] = v.w;
        }
        // Load B tile (16 x 128) direct
#pragma unroll
        for (int u = 0; u < 2; ++u) {
            int idx = u * 256 + tid;
            int row = idx >> 5, c4 = idx & 31; // row 0..15, c4 0..31
            *(float4*)&Bs[row][c4 * 4] =
                *(const float4*)&Bw[(size_t)(k0 + row) * N + n0 + c4 * 4];
        }
        __syncthreads();
#pragma unroll
        for (int kk = 0; kk < 16; ++kk) {
            float af[8], bf[8];
            *(float4*)&af[0] = *(float4*)&As[kk][ty * 8];
            *(float4*)&af[4] = *(float4*)&As[kk][ty * 8 + 4];
            *(float4*)&bf[0] = *(float4*)&Bs[kk][tx * 8];
            *(float4*)&bf[4] = *(float4*)&Bs[kk][tx * 8 + 4];
#pragma unroll
            for (int a = 0; a < 8; ++a)
#pragma unroll
                for (int b = 0; b < 8; ++b)
                    acc[a][b] += af[a] * bf[b];
        }
        __syncthreads();
    }
#pragma unroll
    for (int a = 0; a < 8; ++a) {
#pragma unroll
        for (int b4 = 0; b4 < 2; ++b4) {
            int n = n0 + tx * 8 + b4 * 4;
            float4 o;
            o.x = acc[a][b4 * 4 + 0] + bias[n + 0];
            o.y = acc[a][b4 * 4 + 1] + bias[n + 1];
            o.z = acc[a][b4 * 4 + 2] + bias[n + 2];
            o.w = acc[a][b4 * 4 + 3] + bias[n + 3];
            *(float4*)&Cm[(size_t)(m0 + ty * 8 + a) * N + n] = o;
        }
    }
}

// ---------------------------------------------------------------------------
// Fused causal attention with relative-position scores (flash-style).
// grid: (16 i-tiles, 64 b*h). 256 threads as 16x16, each owns a 4x4 S tile
// and a 4x4 O tile. score(i,j) = (q_i + E[h, clamp(i-j,0)]) . k_j.
// Within a thread's 4x4 tile only 7 distinct E rows are needed (a-b in [-3,3]).
// ---------------------------------------------------------------------------
#define LD 65                 // smem row pitch (floats)
#define SMEM_FLOATS (3 * 64 * LD + 128 * LD)   // Q,K,V (64 rows) + E (128 rows)

__global__ __launch_bounds__(256, 2)
void attn_kernel(const float* __restrict__ rel)
{
    extern __shared__ float sm[];
    float* sQ = sm;                     // 64 x LD
    float* sK = sm + 64 * LD;           // 64 x LD
    float* sV = sm + 2 * 64 * LD;       // 64 x LD
    float* sE = sm + 3 * 64 * LD;       // 128 x LD
    float* sS = sE;                     // alias: P tile reuses E rows 0..63

    const int tid = threadIdx.x;
    const int tx = tid & 15, ty = tid >> 4;
    const int it = blockIdx.x;          // i tile (0..15)
    const int bh = blockIdx.y;          // 0..63
    const int b = bh >> 4, h = bh & 15;
    const int i0 = it * 64;

    const float* qbase = g_qkv + (size_t)b * T_ * C3_ + h * HD_;

    // Load Q tile once (64 rows x 64 d)
#pragma unroll
    for (int u = 0; u < 4; ++u) {
        int idx = u * 256 + tid;         // 0..1023
        int row = idx >> 4, c4 = idx & 15;
        float4 v = *(const float4*)&qbase[(size_t)(i0 + row) * C3_ + c4 * 4];
        float* dst = &sQ[row * LD + c4 * 4];
        dst[0] = v.x; dst[1] = v.y; dst[2] = v.z; dst[3] = v.w;
    }

    float m_[4], l_[4], acc[4][4];
#pragma unroll
    for (int a = 0; a < 4; ++a) {
        m_[a] = -1e30f; l_[a] = 0.f;
#pragma unroll
        for (int bb = 0; bb < 4; ++bb) acc[a][bb] = 0.f;
    }

    const int db3 = (ty - tx) * 4 + 60;  // E row base: rows db3..db3+6 (in [0,126])

    for (int jt = 0; jt <= it; ++jt) {
        const int j0 = jt * 64;
        const int delta = i0 - j0;
        __syncthreads();  // previous iteration's smem reads complete

        // Load K and V tiles (64 x 64 each)
#pragma unroll
        for (int u = 0; u < 4; ++u) {
            int idx = u * 256 + tid;
            int row = idx >> 4, c4 = idx & 15;
            const float* src = &qbase[(size_t)(j0 + row) * C3_ + c4 * 4];
            float4 kv = *(const float4*)&src[C_];
            float4 vv = *(const float4*)&src[2 * C_];
            float* dk = &sK[row * LD + c4 * 4];
            dk[0] = kv.x; dk[1] = kv.y; dk[2] = kv.z; dk[3] = kv.w;
            float* dv = &sV[row * LD + c4 * 4];
            dv[0] = vv.x; dv[1] = vv.y; dv[2] = vv.z; dv[3] = vv.w;
        }
        // Load E tile: 128 rows, row rr -> global r = clamp(delta-63+rr, 0, T-1)
#pragma unroll
        for (int u = 0; u < 8; ++u) {
            int idx = u * 256 + tid;     // 0..2047
            int row = idx >> 4, c4 = idx & 15;
            int r = delta - 63 + row;
            r = min(max(r, 0), T_ - 1);
            float4 ev = *(const float4*)&rel[((size_t)h * T_ + r) * HD_ + c4 * 4];
            float* de = &sE[row * LD + c4 * 4];
            de[0] = ev.x; de[1] = ev.y; de[2] = ev.z; de[3] = ev.w;
        }
        __syncthreads();

        // Scores: s[a][b] = sum_d (q[ii][d] + E[ii-jj+63][d]) * k[jj][d]
        float s[4][4];
#pragma unroll
        for (int a = 0; a < 4; ++a)
#pragma unroll
            for (int bb = 0; bb < 4; ++bb) s[a][bb] = 0.f;

#pragma unroll 8
        for (int d = 0; d < 64; ++d) {
            float kf[4], qf[4], ef[7];
#pragma unroll
            for (int bb = 0; bb < 4; ++bb) kf[bb] = sK[(tx * 4 + bb) * LD + d];
#pragma unroll
            for (int a = 0; a < 4; ++a)   qf[a]  = sQ[(ty * 4 + a) * LD + d];
#pragma unroll
            for (int e = 0; e < 7; ++e)   ef[e]  = sE[(db3 + e) * LD + d];
#pragma unroll
            for (int a = 0; a < 4; ++a)
#pragma unroll
                for (int bb = 0; bb < 4; ++bb)
                    s[a][bb] += (qf[a] + ef[a - bb + 3]) * kf[bb];
        }

        // Scale, causal mask (diagonal tile only), online softmax
        const bool diag = (jt == it);
#pragma unroll
        for (int a = 0; a < 4; ++a) {
            const int ii = ty * 4 + a;
#pragma unroll
            for (int bb = 0; bb < 4; ++bb) {
                s[a][bb] *= 0.125f;   // 1/sqrt(64)
                if (diag && (tx * 4 + bb) > ii) s[a][bb] = -1e30f;
            }
            float mx = fmaxf(fmaxf(s[a][0], s[a][1]), fmaxf(s[a][2], s[a][3]));
#pragma unroll
            for (int off = 8; off > 0; off >>= 1)
                mx = fmaxf(mx, __shfl_xor_sync(0xffffffffu, mx, off));
            float mnew = fmaxf(m_[a], mx);
            float corr = __expf(m_[a] - mnew);
            float rs = 0.f;
#pragma unroll
            for (int bb = 0; bb < 4; ++bb) {
                s[a][bb] = __expf(s[a][bb] - mnew);
                rs += s[a][bb];
            }
#pragma unroll
            for (int off = 8; off > 0; off >>= 1)
                rs += __shfl_xor_sync(0xffffffffu, rs, off);
            l_[a] = l_[a] * corr + rs;
#pragma unroll
            for (int bb = 0; bb < 4; ++bb) acc[a][bb] *= corr;
            m_[a] = mnew;
        }

        __syncthreads();  // all E reads done before aliased write
#pragma unroll
        for (int a = 0; a < 4; ++a)
#pragma unroll
            for (int bb = 0; bb < 4; ++bb)
                sS[(ty * 4 + a) * LD + tx * 4 + bb] = s[a][bb];
        __syncthreads();

        // O += P @ V
#pragma unroll 8
        for (int jj = 0; jj < 64; ++jj) {
            float pr[4], vf[4];
#pragma unroll
            for (int a = 0; a < 4; ++a)  pr[a] = sS[(ty * 4 + a) * LD + jj];
#pragma unroll
            for (int bb = 0; bb < 4; ++bb) vf[bb] = sV[jj * LD + tx * 4 + bb];
#pragma unroll
            for (int a = 0; a < 4; ++a)
#pragma unroll
                for (int bb = 0; bb < 4; ++bb)
                    acc[a][bb] += pr[a] * vf[bb];
        }
    }

    // Write y (B, T, C) with head offset
#pragma unroll
    for (int a = 0; a < 4; ++a) {
        float inv = 1.f / l_[a];
        float4 o;
        o.x = acc[a][0] * inv; o.y = acc[a][1] * inv;
        o.z = acc[a][2] * inv; o.w = acc[a][3] * inv;
        *(float4*)&g_y[((size_t)b * T_ + i0 + ty * 4 + a) * C_ + h * HD_ + tx * 4] = o;
    }
}

// ---------------------------------------------------------------------------
extern "C" void kernel_launch(void* const* d_in, const int* in_sizes, int n_in,
                              void* d_out, int out_size)
{
    (void)in_sizes; (void)n_in; (void)out_size;
    const float* x      = (const float*)d_in[0];
    const float* W_attn = (const float*)d_in[1];
    const float* b_attn = (const float*)d_in[2];
    const float* W_proj = (const float*)d_in[3];
    const float* b_proj = (const float*)d_in[4];
    const float* rel    = (const float*)d_in[5];
    float* out = (float*)d_out;

    float *qkv = nullptr, *y = nullptr;
    cudaGetSymbolAddress((void**)&qkv, g_qkv);
    cudaGetSymbolAddress((void**)&y, g_y);

    const int smem_bytes = SMEM_FLOATS * (int)sizeof(float);
    cudaFuncSetAttribute(attn_kernel,
                         cudaFuncAttributeMaxDynamicSharedMemorySize, smem_bytes);

    // 1) qkv = x @ W_attn + b_attn   (4096 x 3072, K=1024)
    gemm_bias_kernel<<<dim3(C3_ / 128, (B_ * T_) / 128), 256>>>(
        x, W_attn, b_attn, qkv, B_ * T_, C3_, C_);

    // 2) fused causal attention + rel-pos -> g_y
    attn_kernel<<<dim3(T_ / 64, B_ * H_), 256, smem_bytes>>>(rel);

    // 3) out = y @ W_proj + b_proj   (4096 x 1024, K=1024)
    gemm_bias_kernel<<<dim3(C_ / 128, (B_ * T_) / 128), 256>>>(
        y, W_proj, b_proj, out, B_ * T_, C_, C_);
}

// round 3
// speedup vs baseline: 1.5026x; 1.5026x over previous
#include <cuda_runtime.h>
#include <cuda_bf16.h>
#include <math.h>
#include <cstdint>

#define T_  1024
#define C_  1024
#define H_  16
#define HD_ 64
#define B_  4
#define C3_ 3072

// ---------------- scratch (device globals; allocation-free) ----------------
__device__ float g_qkv[(size_t)B_ * T_ * C3_];
__device__ float g_y[(size_t)B_ * T_ * C_];

__device__ __nv_bfloat16 g_xh[(size_t)B_ * T_ * C_];
__device__ __nv_bfloat16 g_xl[(size_t)B_ * T_ * C_];
__device__ __nv_bfloat16 g_yh[(size_t)B_ * T_ * C_];
__device__ __nv_bfloat16 g_yl[(size_t)B_ * T_ * C_];
__device__ __nv_bfloat16 g_wah[(size_t)C3_ * C_];  // W_attn^T [N][K]
__device__ __nv_bfloat16 g_wal[(size_t)C3_ * C_];
__device__ __nv_bfloat16 g_wph[(size_t)C_ * C_];   // W_proj^T [N][K]
__device__ __nv_bfloat16 g_wpl[(size_t)C_ * C_];

// ---------------- warp-level MMA helpers (baseline PTX, no 'a' features) ----
__device__ __forceinline__ uint32_t smem_u32(const void* p) {
    uint32_t a;
    asm("{ .reg .u64 t; cvta.to.shared.u64 t, %1; cvt.u32.u64 %0, t; }" : "=r"(a) : "l"(p));
    return a;
}
__device__ __forceinline__ void ldsm4(uint32_t* r, uint32_t addr) {
    asm volatile("ldmatrix.sync.aligned.m8n8.x4.shared.b16 {%0,%1,%2,%3}, [%4];"
                 : "=r"(r[0]), "=r"(r[1]), "=r"(r[2]), "=r"(r[3]) : "r"(addr));
}
__device__ __forceinline__ void mma16816(float* c, const uint32_t* a, const uint32_t* b) {
    asm volatile("mma.sync.aligned.m16n8k16.row.col.f32.bf16.bf16.f32 "
                 "{%0,%1,%2,%3}, {%4,%5,%6,%7}, {%8,%9}, {%0,%1,%2,%3};"
                 : "+f"(c[0]), "+f"(c[1]), "+f"(c[2]), "+f"(c[3])
                 : "r"(a[0]), "r"(a[1]), "r"(a[2]), "r"(a[3]), "r"(b[0]), "r"(b[1]));
}

// ---------------------------------------------------------------------------
// Split-bf16 HMMA GEMM: out[M,N] = A[M,K] @ B[N,K]^T + bias (fp32 result)
// A as (Ah,Al) [M][K] bf16; B as (Bh,Bl) [N][K] bf16. Tile 128x128, Kc=32.
// 8 warps (2x4), warp tile 64x32. Pitch 40 bf16 -> ldmatrix conflict-free.
// ---------------------------------------------------------------------------
#define PITCH 40
#define TILE_ELEMS (128 * PITCH)

__global__ __launch_bounds__(256, 2)
void gemm_mma_kernel(const __nv_bfloat16* __restrict__ Ah, const __nv_bfloat16* __restrict__ Al,
                     const __nv_bfloat16* __restrict__ Bh, const __nv_bfloat16* __restrict__ Bl,
                     const float* __restrict__ bias, float* __restrict__ out,
                     int M, int N, int K)
{
    __shared__ __nv_bfloat16 smem[4 * TILE_ELEMS];
    const uint32_t sb = smem_u32(smem);
    const uint32_t sAh = sb, sAl = sb + TILE_ELEMS * 2,
                   sBh = sb + 2 * TILE_ELEMS * 2, sBl = sb + 3 * TILE_ELEMS * 2;

    const int tid = threadIdx.x;
    const int wid = tid >> 5, lane = tid & 31;
    const int wr = wid >> 2, wc = wid & 3;     // 2 x 4 warp grid
    const int m0 = blockIdx.y * 128, n0g = blockIdx.x * 128;

    float acc[4][4][4];
#pragma unroll
    for (int mt = 0; mt < 4; ++mt)
#pragma unroll
        for (int nt = 0; nt < 4; ++nt)
#pragma unroll
            for (int i = 0; i < 4; ++i) acc[mt][nt][i] = 0.f;

    // ldmatrix per-lane address components (in bf16 elements)
    const int a_row = (lane & 15);                       // + warp/mt base
    const int a_col = (lane >> 4) << 3;                  // 0 or 8
    const int b_row = (lane & 7) + ((lane >> 4) << 3);   // n within 16
    const int b_col = (lane & 8);                        // 0 or 8

    const char* gsrc[4] = {
        (const char*)(Ah + (size_t)m0 * K),
        (const char*)(Al + (size_t)m0 * K),
        (const char*)(Bh + (size_t)n0g * K),
        (const char*)(Bl + (size_t)n0g * K) };
    const size_t rowb = (size_t)K * 2;

    const int nch = K / 32;
    for (int ch = 0; ch < nch; ++ch) {
        const size_t kb = (size_t)ch * 64;  // 32 bf16 = 64 B
        // stage 4 tiles: 128 rows x 32 bf16 each
#pragma unroll
        for (int t = 0; t < 4; ++t) {
            __nv_bfloat16* dst = smem + t * TILE_ELEMS;
            const char* src = gsrc[t] + kb;
#pragma unroll
            for (int u = 0; u < 2; ++u) {
                int idx = u * 256 + tid;          // 0..511
                int r = idx >> 2, c = idx & 3;    // c: 16B unit
                uint4 v = *(const uint4*)(src + (size_t)r * rowb + c * 16);
                *(uint4*)((char*)(dst + r * PITCH) + c * 16) = v;
            }
        }
        __syncthreads();

#pragma unroll
        for (int ks = 0; ks < 2; ++ks) {
            const int kofs = ks * 16;
            uint32_t Af[4][4], Bf[2][4];
            // A rows for this warp: wr*64 + mt*16; B n for this warp: wc*32 + nt2*16
#pragma unroll
            for (int mt = 0; mt < 4; ++mt)
                ldsm4(Af[mt], sAh + ((wr * 64 + mt * 16 + a_row) * PITCH + kofs + a_col) * 2);
#pragma unroll
            for (int nt2 = 0; nt2 < 2; ++nt2)
                ldsm4(Bf[nt2], sBl + ((wc * 32 + nt2 * 16 + b_row) * PITCH + kofs + b_col) * 2);
#pragma unroll
            for (int mt = 0; mt < 4; ++mt)
#pragma unroll
                for (int nt = 0; nt < 4; ++nt)
                    mma16816(acc[mt][nt], Af[mt], &Bf[nt >> 1][(nt & 1) * 2]);  // hi*lo

#pragma unroll
            for (int nt2 = 0; nt2 < 2; ++nt2)
                ldsm4(Bf[nt2], sBh + ((wc * 32 + nt2 * 16 + b_row) * PITCH + kofs + b_col) * 2);
#pragma unroll
            for (int mt = 0; mt < 4; ++mt)
#pragma unroll
                for (int nt = 0; nt < 4; ++nt)
                    mma16816(acc[mt][nt], Af[mt], &Bf[nt >> 1][(nt & 1) * 2]);  // hi*hi

#pragma unroll
            for (int mt = 0; mt < 4; ++mt)
                ldsm4(Af[mt], sAl + ((wr * 64 + mt * 16 + a_row) * PITCH + kofs + a_col) * 2);
#pragma unroll
            for (int mt = 0; mt < 4; ++mt)
#pragma unroll
                for (int nt = 0; nt < 4; ++nt)
                    mma16816(acc[mt][nt], Af[mt], &Bf[nt >> 1][(nt & 1) * 2]);  // lo*hi
        }
        __syncthreads();
    }

    // epilogue
    const int qr = lane >> 2, qc = (lane & 3) * 2;
#pragma unroll
    for (int mt = 0; mt < 4; ++mt) {
        const int row = m0 + wr * 64 + mt * 16 + qr;
#pragma unroll
        for (int nt = 0; nt < 4; ++nt) {
            const int col = n0g + wc * 32 + nt * 8 + qc;
            const float b0 = bias[col], b1 = bias[col + 1];
            float2 o0 = {acc[mt][nt][0] + b0, acc[mt][nt][1] + b1};
            float2 o1 = {acc[mt][nt][2] + b0, acc[mt][nt][3] + b1};
            *(float2*)&out[(size_t)row * N + col] = o0;
            *(float2*)&out[(size_t)(row + 8) * N + col] = o1;
        }
    }
}

// ---------------------------------------------------------------------------
// Prep kernels
// ---------------------------------------------------------------------------
__global__ void split_kernel(const float* __restrict__ src,
                             __nv_bfloat16* __restrict__ hi,
                             __nv_bfloat16* __restrict__ lo, int n4)
{
    int i = blockIdx.x * blockDim.x + threadIdx.x;
    if (i >= n4) return;
    float4 v = *(const float4*)(src + (size_t)i * 4);
    __nv_bfloat16 h0 = __float2bfloat16(v.x), h1 = __float2bfloat16(v.y);
    __nv_bfloat16 h2 = __float2bfloat16(v.z), h3 = __float2bfloat16(v.w);
    __nv_bfloat16 l0 = __float2bfloat16(v.x - __bfloat162float(h0));
    __nv_bfloat16 l1 = __float2bfloat16(v.y - __bfloat162float(h1));
    __nv_bfloat16 l2 = __float2bfloat16(v.z - __bfloat162float(h2));
    __nv_bfloat16 l3 = __float2bfloat16(v.w - __bfloat162float(h3));
    ((__nv_bfloat162*)hi)[i * 2 + 0] = __nv_bfloat162(h0, h1);
    ((__nv_bfloat162*)hi)[i * 2 + 1] = __nv_bfloat162(h2, h3);
    ((__nv_bfloat162*)lo)[i * 2 + 0] = __nv_bfloat162(l0, l1);
    ((__nv_bfloat162*)lo)[i * 2 + 1] = __nv_bfloat162(l2, l3);
}

// W: [K][N] row-major -> hi/lo: [N][K]
__global__ void transpose_split_kernel(const float* __restrict__ W,
                                       __nv_bfloat16* __restrict__ th,
                                       __nv_bfloat16* __restrict__ tl, int K, int N)
{
    __shared__ float tile[32][33];
    const int tx = threadIdx.x, ty = threadIdx.y;
    const int n0 = blockIdx.x * 32, k0 = blockIdx.y * 32;
#pragma unroll
    for (int j = 0; j < 4; ++j)
        tile[ty + j * 8][tx] = W[(size_t)(k0 + ty + j * 8) * N + n0 + tx];
    __syncthreads();
#pragma unroll
    for (int j = 0; j < 4; ++j) {
        float v = tile[tx][ty + j * 8];
        __nv_bfloat16 h = __float2bfloat16(v);
        __nv_bfloat16 l = __float2bfloat16(v - __bfloat162float(h));
        size_t o = (size_t)(n0 + ty + j * 8) * K + k0 + tx;
        th[o] = h; tl[o] = l;
    }
}

// ---------------------------------------------------------------------------
// Fused causal attention with rel-pos (fp32 SIMT, from R1)
// ---------------------------------------------------------------------------
#define LD 65
#define ATTN_SMEM_FLOATS (3 * 64 * LD + 128 * LD)

__global__ __launch_bounds__(256, 2)
void attn_kernel(const float* __restrict__ rel)
{
    extern __shared__ float smf[];
    float* sQ = smf;
    float* sK = smf + 64 * LD;
    float* sV = smf + 2 * 64 * LD;
    float* sE = smf + 3 * 64 * LD;
    float* sS = sE;

    const int tid = threadIdx.x;
    const int tx = tid & 15, ty = tid >> 4;
    const int it = blockIdx.x;
    const int bh = blockIdx.y;
    const int b = bh >> 4, h = bh & 15;
    const int i0 = it * 64;

    const float* qbase = g_qkv + (size_t)b * T_ * C3_ + h * HD_;

#pragma unroll
    for (int u = 0; u < 4; ++u) {
        int idx = u * 256 + tid;
        int row = idx >> 4, c4 = idx & 15;
        float4 v = *(const float4*)&qbase[(size_t)(i0 + row) * C3_ + c4 * 4];
        float* dst = &sQ[row * LD + c4 * 4];
        dst[0] = v.x; dst[1] = v.y; dst[2] = v.z; dst[3] = v.w;
    }

    float m_[4], l_[4], acc[4][4];
#pragma unroll
    for (int a = 0; a < 4; ++a) {
        m_[a] = -1e30f; l_[a] = 0.f;
#pragma unroll
        for (int bb = 0; bb < 4; ++bb) acc[a][bb] = 0.f;
    }

    const int db3 = (ty - tx) * 4 + 60;

    for (int jt = 0; jt <= it; ++jt) {
        const int j0 = jt * 64;
        const int delta = i0 - j0;
        __syncthreads();

#pragma unroll
        for (int u = 0; u < 4; ++u) {
            int idx = u * 256 + tid;
            int row = idx >> 4, c4 = idx & 15;
            const float* src = &qbase[(size_t)(j0 + row) * C3_ + c4 * 4];
            float4 kv = *(const float4*)&src[C_];
            float4 vv = *(const float4*)&src[2 * C_];
            float* dk = &sK[row * LD + c4 * 4];
            dk[0] = kv.x; dk[1] = kv.y; dk[2] = kv.z; dk[3] = kv.w;
            float* dv = &sV[row * LD + c4 * 4];
            dv[0] = vv.x; dv[1] = vv.y; dv[2] = vv.z; dv[3] = vv.w;
        }
#pragma unroll
        for (int u = 0; u < 8; ++u) {
            int idx = u * 256 + tid;
            int row = idx >> 4, c4 = idx & 15;
            int r = delta - 63 + row;
            r = min(max(r, 0), T_ - 1);
            float4 ev = *(const float4*)&rel[((size_t)h * T_ + r) * HD_ + c4 * 4];
            float* de = &sE[row * LD + c4 * 4];
            de[0] = ev.x; de[1] = ev.y; de[2] = ev.z; de[3] = ev.w;
        }
        __syncthreads();

        float s[4][4];
#pragma unroll
        for (int a = 0; a < 4; ++a)
#pragma unroll
            for (int bb = 0; bb < 4; ++bb) s[a][bb] = 0.f;

#pragma unroll 8
        for (int d = 0; d < 64; ++d) {
            float kf[4], qf[4], ef[7];
#pragma unroll
            for (int bb = 0; bb < 4; ++bb) kf[bb] = sK[(tx * 4 + bb) * LD + d];
#pragma unroll
            for (int a = 0; a < 4; ++a)   qf[a]  = sQ[(ty * 4 + a) * LD + d];
#pragma unroll
            for (int e = 0; e < 7; ++e)   ef[e]  = sE[(db3 + e) * LD + d];
#pragma unroll
            for (int a = 0; a < 4; ++a)
#pragma unroll
                for (int bb = 0; bb < 4; ++bb)
                    s[a][bb] += (qf[a] + ef[a - bb + 3]) * kf[bb];
        }

        const bool diag = (jt == it);
#pragma unroll
        for (int a = 0; a < 4; ++a) {
            const int ii = ty * 4 + a;
#pragma unroll
            for (int bb = 0; bb < 4; ++bb) {
                s[a][bb] *= 0.125f;
                if (diag && (tx * 4 + bb) > ii) s[a][bb] = -1e30f;
            }
            float mx = fmaxf(fmaxf(s[a][0], s[a][1]), fmaxf(s[a][2], s[a][3]));
#pragma unroll
            for (int off = 8; off > 0; off >>= 1)
                mx = fmaxf(mx, __shfl_xor_sync(0xffffffffu, mx, off));
            float mnew = fmaxf(m_[a], mx);
            float corr = __expf(m_[a] - mnew);
            float rs = 0.f;
#pragma unroll
            for (int bb = 0; bb < 4; ++bb) {
                s[a][bb] = __expf(s[a][bb] - mnew);
                rs += s[a][bb];
            }
#pragma unroll
            for (int off = 8; off > 0; off >>= 1)
                rs += __shfl_xor_sync(0xffffffffu, rs, off);
            l_[a] = l_[a] * corr + rs;
#pragma unroll
            for (int bb = 0; bb < 4; ++bb) acc[a][bb] *= corr;
            m_[a] = mnew;
        }

        __syncthreads();
#pragma unroll
        for (int a = 0; a < 4; ++a)
#pragma unroll
            for (int bb = 0; bb < 4; ++bb)
                sS[(ty * 4 + a) * LD + tx * 4 + bb] = s[a][bb];
        __syncthreads();

#pragma unroll 8
        for (int jj = 0; jj < 64; ++jj) {
            float pr[4], vf[4];
#pragma unroll
            for (int a = 0; a < 4; ++a)  pr[a] = sS[(ty * 4 + a) * LD + jj];
#pragma unroll
            for (int bb = 0; bb < 4; ++bb) vf[bb] = sV[jj * LD + tx * 4 + bb];
#pragma unroll
            for (int a = 0; a < 4; ++a)
#pragma unroll
                for (int bb = 0; bb < 4; ++bb)
                    acc[a][bb] += pr[a] * vf[bb];
        }
    }

#pragma unroll
    for (int a = 0; a < 4; ++a) {
        float inv = 1.f / l_[a];
        float4 o;
        o.x = acc[a][0] * inv; o.y = acc[a][1] * inv;
        o.z = acc[a][2] * inv; o.w = acc[a][3] * inv;
        *(float4*)&g_y[((size_t)b * T_ + i0 + ty * 4 + a) * C_ + h * HD_ + tx * 4] = o;
    }
}

// ---------------------------------------------------------------------------
extern "C" void kernel_launch(void* const* d_in, const int* in_sizes, int n_in,
                              void* d_out, int out_size)
{
    (void)in_sizes; (void)n_in; (void)out_size;
    const float* x      = (const float*)d_in[0];
    const float* W_attn = (const float*)d_in[1];
    const float* b_attn = (const float*)d_in[2];
    const float* W_proj = (const float*)d_in[3];
    const float* b_proj = (const float*)d_in[4];
    const float* rel    = (const float*)d_in[5];
    float* out = (float*)d_out;

    float *qkv = nullptr, *y = nullptr;
    __nv_bfloat16 *xh, *xl, *yh, *yl, *wah, *wal, *wph, *wpl;
    cudaGetSymbolAddress((void**)&qkv, g_qkv);
    cudaGetSymbolAddress((void**)&y,   g_y);
    cudaGetSymbolAddress((void**)&xh,  g_xh);
    cudaGetSymbolAddress((void**)&xl,  g_xl);
    cudaGetSymbolAddress((void**)&yh,  g_yh);
    cudaGetSymbolAddress((void**)&yl,  g_yl);
    cudaGetSymbolAddress((void**)&wah, g_wah);
    cudaGetSymbolAddress((void**)&wal, g_wal);
    cudaGetSymbolAddress((void**)&wph, g_wph);
    cudaGetSymbolAddress((void**)&wpl, g_wpl);

    const int attn_smem = ATTN_SMEM_FLOATS * (int)sizeof(float);
    cudaFuncSetAttribute(attn_kernel,
                         cudaFuncAttributeMaxDynamicSharedMemorySize, attn_smem);

    // prep: split x, transpose+split weights
    {
        int n4 = B_ * T_ * C_ / 4;
        split_kernel<<<(n4 + 255) / 256, 256>>>(x, xh, xl, n4);
        transpose_split_kernel<<<dim3(C3_ / 32, C_ / 32), dim3(32, 8)>>>(W_attn, wah, wal, C_, C3_);
        transpose_split_kernel<<<dim3(C_ / 32, C_ / 32), dim3(32, 8)>>>(W_proj, wph, wpl, C_, C_);
    }

    // 1) qkv = x @ W_attn + b_attn   (HMMA split-bf16)
    gemm_mma_kernel<<<dim3(C3_ / 128, (B_ * T_) / 128), 256>>>(
        xh, xl, wah, wal, b_attn, qkv, B_ * T_, C3_, C_);

    // 2) fused causal attention + rel-pos -> g_y
    attn_kernel<<<dim3(T_ / 64, B_ * H_), 256, attn_smem>>>(rel);

    // 3) split y, then out = y @ W_proj + b_proj
    {
        int n4 = B_ * T_ * C_ / 4;
        split_kernel<<<(n4 + 255) / 256, 256>>>(y, yh, yl, n4);
    }
    gemm_mma_kernel<<<dim3(C_ / 128, (B_ * T_) / 128), 256>>>(
        yh, yl, wph, wpl, b_proj, out, B_ * T_, C_, C_);
}

// round 7
// speedup vs baseline: 2.5013x; 1.6647x over previous
#include <cuda_runtime.h>
#include <cuda_bf16.h>
#include <math.h>
#include <cstdint>

#define T_  1024
#define C_  1024
#define H_  16
#define HD_ 64
#define B_  4
#define C3_ 3072

// ---------------- scratch (device globals; allocation-free) ----------------
__device__ float g_qkv[(size_t)B_ * T_ * C3_];

__device__ __nv_bfloat16 g_xh[(size_t)B_ * T_ * C_];
__device__ __nv_bfloat16 g_xl[(size_t)B_ * T_ * C_];
__device__ __nv_bfloat16 g_yh[(size_t)B_ * T_ * C_];
__device__ __nv_bfloat16 g_yl[(size_t)B_ * T_ * C_];
__device__ __nv_bfloat16 g_wah[(size_t)C3_ * C_];
__device__ __nv_bfloat16 g_wal[(size_t)C3_ * C_];
__device__ __nv_bfloat16 g_wph[(size_t)C_ * C_];
__device__ __nv_bfloat16 g_wpl[(size_t)C_ * C_];

// per-head split arrays: [bh][t][d] for q,k ; [bh][d][t] for v ; [h][r][d] for E
__device__ __nv_bfloat16 g_qh[(size_t)B_ * H_ * T_ * HD_];
__device__ __nv_bfloat16 g_ql[(size_t)B_ * H_ * T_ * HD_];
__device__ __nv_bfloat16 g_kh[(size_t)B_ * H_ * T_ * HD_];
__device__ __nv_bfloat16 g_kl[(size_t)B_ * H_ * T_ * HD_];
__device__ __nv_bfloat16 g_vth[(size_t)B_ * H_ * HD_ * T_];
__device__ __nv_bfloat16 g_vtl[(size_t)B_ * H_ * HD_ * T_];
__device__ __nv_bfloat16 g_eh[(size_t)H_ * T_ * HD_];

// ---------------- warp MMA helpers (baseline PTX) ----------------
__device__ __forceinline__ uint32_t smem_u32(const void* p) {
    uint32_t a;
    asm("{ .reg .u64 t; cvta.to.shared.u64 t, %1; cvt.u32.u64 %0, t; }" : "=r"(a) : "l"(p));
    return a;
}
__device__ __forceinline__ void ldsm4(uint32_t* r, uint32_t addr) {
    asm volatile("ldmatrix.sync.aligned.m8n8.x4.shared.b16 {%0,%1,%2,%3}, [%4];"
                 : "=r"(r[0]), "=r"(r[1]), "=r"(r[2]), "=r"(r[3]) : "r"(addr));
}
__device__ __forceinline__ void mma16816(float* c, const uint32_t* a, const uint32_t* b) {
    asm volatile("mma.sync.aligned.m16n8k16.row.col.f32.bf16.bf16.f32 "
                 "{%0,%1,%2,%3}, {%4,%5,%6,%7}, {%8,%9}, {%0,%1,%2,%3};"
                 : "+f"(c[0]), "+f"(c[1]), "+f"(c[2]), "+f"(c[3])
                 : "r"(a[0]), "r"(a[1]), "r"(a[2]), "r"(a[3]), "r"(b[0]), "r"(b[1]));
}
__device__ __forceinline__ __nv_bfloat162 split_hi2(float a, float b) {
    return __nv_bfloat162(__float2bfloat16(a), __float2bfloat16(b));
}
__device__ __forceinline__ __nv_bfloat162 split_lo2(float a, float b) {
    __nv_bfloat16 ha = __float2bfloat16(a), hb = __float2bfloat16(b);
    return __nv_bfloat162(__float2bfloat16(a - __bfloat162float(ha)),
                          __float2bfloat16(b - __bfloat162float(hb)));
}

// ---------------------------------------------------------------------------
// Split-bf16 HMMA GEMM (from R3): out[M,N] = A@B^T + bias
// ---------------------------------------------------------------------------
#define PITCH 40
#define TILE_ELEMS (128 * PITCH)

__global__ __launch_bounds__(256, 2)
void gemm_mma_kernel(const __nv_bfloat16* __restrict__ Ah, const __nv_bfloat16* __restrict__ Al,
                     const __nv_bfloat16* __restrict__ Bh, const __nv_bfloat16* __restrict__ Bl,
                     const float* __restrict__ bias, float* __restrict__ out,
                     int M, int N, int K)
{
    __shared__ __nv_bfloat16 smem[4 * TILE_ELEMS];
    const uint32_t sb = smem_u32(smem);
    const uint32_t sAh = sb, sAl = sb + TILE_ELEMS * 2,
                   sBh = sb + 2 * TILE_ELEMS * 2, sBl = sb + 3 * TILE_ELEMS * 2;

    const int tid = threadIdx.x;
    const int wid = tid >> 5, lane = tid & 31;
    const int wr = wid >> 2, wc = wid & 3;
    const int m0 = blockIdx.y * 128, n0g = blockIdx.x * 128;

    float acc[4][4][4];
#pragma unroll
    for (int mt = 0; mt < 4; ++mt)
#pragma unroll
        for (int nt = 0; nt < 4; ++nt)
#pragma unroll
            for (int i = 0; i < 4; ++i) acc[mt][nt][i] = 0.f;

    const int a_row = (lane & 15);
    const int a_col = (lane >> 4) << 3;
    const int b_row = (lane & 7) + ((lane >> 4) << 3);
    const int b_col = (lane & 8);

    const char* gsrc[4] = {
        (const char*)(Ah + (size_t)m0 * K),
        (const char*)(Al + (size_t)m0 * K),
        (const char*)(Bh + (size_t)n0g * K),
        (const char*)(Bl + (size_t)n0g * K) };
    const size_t rowb = (size_t)K * 2;

    const int nch = K / 32;
    for (int ch = 0; ch < nch; ++ch) {
        const size_t kb = (size_t)ch * 64;
#pragma unroll
        for (int t = 0; t < 4; ++t) {
            __nv_bfloat16* dst = smem + t * TILE_ELEMS;
            const char* src = gsrc[t] + kb;
#pragma unroll
            for (int u = 0; u < 2; ++u) {
                int idx = u * 256 + tid;
                int r = idx >> 2, c = idx & 3;
                uint4 v = *(const uint4*)(src + (size_t)r * rowb + c * 16);
                *(uint4*)((char*)(dst + r * PITCH) + c * 16) = v;
            }
        }
        __syncthreads();

#pragma unroll
        for (int ks = 0; ks < 2; ++ks) {
            const int kofs = ks * 16;
            uint32_t Af[4][4], Bf[2][4];
#pragma unroll
            for (int mt = 0; mt < 4; ++mt)
                ldsm4(Af[mt], sAh + ((wr * 64 + mt * 16 + a_row) * PITCH + kofs + a_col) * 2);
#pragma unroll
            for (int nt2 = 0; nt2 < 2; ++nt2)
                ldsm4(Bf[nt2], sBl + ((wc * 32 + nt2 * 16 + b_row) * PITCH + kofs + b_col) * 2);
#pragma unroll
            for (int mt = 0; mt < 4; ++mt)
#pragma unroll
                for (int nt = 0; nt < 4; ++nt)
                    mma16816(acc[mt][nt], Af[mt], &Bf[nt >> 1][(nt & 1) * 2]);

#pragma unroll
            for (int nt2 = 0; nt2 < 2; ++nt2)
                ldsm4(Bf[nt2], sBh + ((wc * 32 + nt2 * 16 + b_row) * PITCH + kofs + b_col) * 2);
#pragma unroll
            for (int mt = 0; mt < 4; ++mt)
#pragma unroll
                for (int nt = 0; nt < 4; ++nt)
                    mma16816(acc[mt][nt], Af[mt], &Bf[nt >> 1][(nt & 1) * 2]);

#pragma unroll
            for (int mt = 0; mt < 4; ++mt)
                ldsm4(Af[mt], sAl + ((wr * 64 + mt * 16 + a_row) * PITCH + kofs + a_col) * 2);
#pragma unroll
            for (int mt = 0; mt < 4; ++mt)
#pragma unroll
                for (int nt = 0; nt < 4; ++nt)
                    mma16816(acc[mt][nt], Af[mt], &Bf[nt >> 1][(nt & 1) * 2]);
        }
        __syncthreads();
    }

    const int qr = lane >> 2, qc = (lane & 3) * 2;
#pragma unroll
    for (int mt = 0; mt < 4; ++mt) {
        const int row = m0 + wr * 64 + mt * 16 + qr;
#pragma unroll
        for (int nt = 0; nt < 4; ++nt) {
            const int col = n0g + wc * 32 + nt * 8 + qc;
            const float b0 = bias[col], b1 = bias[col + 1];
            float2 o0 = {acc[mt][nt][0] + b0, acc[mt][nt][1] + b1};
            float2 o1 = {acc[mt][nt][2] + b0, acc[mt][nt][3] + b1};
            *(float2*)&out[(size_t)row * N + col] = o0;
            *(float2*)&out[(size_t)(row + 8) * N + col] = o1;
        }
    }
}

// ---------------------------------------------------------------------------
// MMA flash attention with rel-pos.
// grid (64 bh, 16 i-tiles), 128 threads (4 warps). i-tile 64, j-tile 64.
// ---------------------------------------------------------------------------
#define PA 72      // bf16 smem pitch (elements); row = 144 B
#define PS2 66     // fp32 pitch for S2 band

#define SO_QE  0
#define SO_QL  9216
#define SO_K   18432
#define SO_KL  27648
#define SO_V   36864
#define SO_VL  46080
#define SO_S2  55296
#define SO_P   89088
#define SO_PL  98304
#define ATTN_SMEM_BYTES 107520

__global__ __launch_bounds__(128, 2)
void attn_mma_kernel()
{
    extern __shared__ char sm[];
    const uint32_t sb = smem_u32(sm);
    float* s2f = (float*)(sm + SO_S2);

    const int tid = threadIdx.x, lane = tid & 31, w = tid >> 5;
    const int bh = blockIdx.x, h = bh & 15, b = bh >> 4;
    const int it = 15 - (int)blockIdx.y, i0 = it * 64;

    const int qr = lane >> 2, qc = (lane & 3) * 2;
    const int a_row = lane & 15, a_col = (lane >> 4) << 3;
    const int b_row = (lane & 7) + ((lane >> 4) << 3), b_col = lane & 8;

    // ---- stage Q (hi/lo) and load Q frags once ----
    {
        const char* sqh = (const char*)(g_qh + ((size_t)bh * T_ + i0) * HD_);
        const char* sql = (const char*)(g_ql + ((size_t)bh * T_ + i0) * HD_);
#pragma unroll
        for (int u = 0; u < 4; ++u) {
            int idx = u * 128 + tid;
            int r = idx >> 3, c = idx & 7;
            *(uint4*)(sm + SO_QE + r * 144 + c * 16) = *(const uint4*)(sqh + r * 128 + c * 16);
            *(uint4*)(sm + SO_QL + r * 144 + c * 16) = *(const uint4*)(sql + r * 128 + c * 16);
        }
    }
    __syncthreads();
    uint32_t Aqh[4][4], Aql[4][4];
#pragma unroll
    for (int ks = 0; ks < 4; ++ks) {
        ldsm4(Aqh[ks], sb + SO_QE + ((w * 16 + a_row) * PA + ks * 16 + a_col) * 2);
        ldsm4(Aql[ks], sb + SO_QL + ((w * 16 + a_row) * PA + ks * 16 + a_col) * 2);
    }

    float o[8][4];
#pragma unroll
    for (int nt = 0; nt < 8; ++nt)
#pragma unroll
        for (int e = 0; e < 4; ++e) o[nt][e] = 0.f;
    float m0r = -1e30f, m1r = -1e30f, l0r = 0.f, l1r = 0.f;

    const int iiA = w * 16 + qr, iiB = iiA + 8;

    for (int jt = 0; jt <= it; ++jt) {
        const int j0 = jt * 64;
        const int delta = i0 - j0;
        __syncthreads();   // smem free: Q frags done / prev PV done

        // ---- load K, V, E tiles ----
        {
            const char* kh = (const char*)(g_kh + ((size_t)bh * T_ + j0) * HD_);
            const char* kl = (const char*)(g_kl + ((size_t)bh * T_ + j0) * HD_);
#pragma unroll
            for (int u = 0; u < 4; ++u) {
                int idx = u * 128 + tid;
                int r = idx >> 3, c = idx & 7;
                *(uint4*)(sm + SO_K  + r * 144 + c * 16) = *(const uint4*)(kh + r * 128 + c * 16);
                *(uint4*)(sm + SO_KL + r * 144 + c * 16) = *(const uint4*)(kl + r * 128 + c * 16);
            }
            const char* vh = (const char*)(g_vth + (size_t)bh * HD_ * T_ + j0);
            const char* vl = (const char*)(g_vtl + (size_t)bh * HD_ * T_ + j0);
#pragma unroll
            for (int u = 0; u < 4; ++u) {
                int idx = u * 128 + tid;
                int r = idx >> 3, c = idx & 7;   // r = d row; global row stride = T_*2 bytes
                *(uint4*)(sm + SO_V  + r * 144 + c * 16) = *(const uint4*)(vh + (size_t)r * (T_ * 2) + c * 16);
                *(uint4*)(sm + SO_VL + r * 144 + c * 16) = *(const uint4*)(vl + (size_t)r * (T_ * 2) + c * 16);
            }
            const char* ep = (const char*)(g_eh + (size_t)h * T_ * HD_);
#pragma unroll
            for (int u = 0; u < 8; ++u) {
                int idx = u * 128 + tid;
                int r = idx >> 3, c = idx & 7;
                int er = delta - 63 + r;
                er = min(max(er, 0), T_ - 1);
                *(uint4*)(sm + SO_QE + r * 144 + c * 16) = *(const uint4*)(ep + (size_t)er * 128 + c * 16);
            }
        }
        __syncthreads();

        // ---- phase A: S2 = E(128x64) @ K^T, store to smem ----
        {
            float s2a[2][8][4];
#pragma unroll
            for (int mt = 0; mt < 2; ++mt)
#pragma unroll
                for (int nt = 0; nt < 8; ++nt)
#pragma unroll
                    for (int e = 0; e < 4; ++e) s2a[mt][nt][e] = 0.f;
#pragma unroll
            for (int ks = 0; ks < 4; ++ks) {
                uint32_t Ea[2][4], Kb[4][4];
#pragma unroll
                for (int mt = 0; mt < 2; ++mt)
                    ldsm4(Ea[mt], sb + SO_QE + ((w * 32 + mt * 16 + a_row) * PA + ks * 16 + a_col) * 2);
#pragma unroll
                for (int nt2 = 0; nt2 < 4; ++nt2)
                    ldsm4(Kb[nt2], sb + SO_K + ((nt2 * 16 + b_row) * PA + ks * 16 + b_col) * 2);
#pragma unroll
                for (int mt = 0; mt < 2; ++mt)
#pragma unroll
                    for (int nt = 0; nt < 8; ++nt)
                        mma16816(s2a[mt][nt], Ea[mt], &Kb[nt >> 1][(nt & 1) * 2]);
            }
#pragma unroll
            for (int mt = 0; mt < 2; ++mt) {
                const int r0 = w * 32 + mt * 16 + qr;
#pragma unroll
                for (int nt = 0; nt < 8; ++nt) {
                    const int col = nt * 8 + qc;
                    *(float2*)(s2f + r0 * PS2 + col) = make_float2(s2a[mt][nt][0], s2a[mt][nt][1]);
                    *(float2*)(s2f + (r0 + 8) * PS2 + col) = make_float2(s2a[mt][nt][2], s2a[mt][nt][3]);
                }
            }
        }

        // ---- phase B: S1 = Q @ K^T (3-term split) ----
        float p[8][4];
#pragma unroll
        for (int nt = 0; nt < 8; ++nt)
#pragma unroll
            for (int e = 0; e < 4; ++e) p[nt][e] = 0.f;
#pragma unroll
        for (int ks = 0; ks < 4; ++ks) {
            uint32_t Kbh[4][4], Kbl[4][4];
#pragma unroll
            for (int nt2 = 0; nt2 < 4; ++nt2) {
                ldsm4(Kbh[nt2], sb + SO_K  + ((nt2 * 16 + b_row) * PA + ks * 16 + b_col) * 2);
                ldsm4(Kbl[nt2], sb + SO_KL + ((nt2 * 16 + b_row) * PA + ks * 16 + b_col) * 2);
            }
#pragma unroll
            for (int nt = 0; nt < 8; ++nt) {
                mma16816(p[nt], Aqh[ks], &Kbh[nt >> 1][(nt & 1) * 2]);
                mma16816(p[nt], Aqh[ks], &Kbl[nt >> 1][(nt & 1) * 2]);
                mma16816(p[nt], Aql[ks], &Kbh[nt >> 1][(nt & 1) * 2]);
            }
        }
        __syncthreads();   // s2 visible to all

        // ---- softmax: gather S2, scale, mask, online update ----
        const bool diag = (jt == it);
        float mx0 = -1e30f, mx1 = -1e30f;
#pragma unroll
        for (int nt = 0; nt < 8; ++nt) {
            const int jj0 = nt * 8 + qc;
            float v0 = (p[nt][0] + s2f[(63 + iiA - jj0) * PS2 + jj0]) * 0.125f;
            float v1 = (p[nt][1] + s2f[(62 + iiA - jj0) * PS2 + jj0 + 1]) * 0.125f;
            float v2 = (p[nt][2] + s2f[(63 + iiB - jj0) * PS2 + jj0]) * 0.125f;
            float v3 = (p[nt][3] + s2f[(62 + iiB - jj0) * PS2 + jj0 + 1]) * 0.125f;
            if (diag) {
                if (jj0 > iiA) v0 = -1e30f;
                if (jj0 + 1 > iiA) v1 = -1e30f;
                if (jj0 > iiB) v2 = -1e30f;
                if (jj0 + 1 > iiB) v3 = -1e30f;
            }
            p[nt][0] = v0; p[nt][1] = v1; p[nt][2] = v2; p[nt][3] = v3;
            mx0 = fmaxf(mx0, fmaxf(v0, v1));
            mx1 = fmaxf(mx1, fmaxf(v2, v3));
        }
        mx0 = fmaxf(mx0, __shfl_xor_sync(0xffffffffu, mx0, 1));
        mx0 = fmaxf(mx0, __shfl_xor_sync(0xffffffffu, mx0, 2));
        mx1 = fmaxf(mx1, __shfl_xor_sync(0xffffffffu, mx1, 1));
        mx1 = fmaxf(mx1, __shfl_xor_sync(0xffffffffu, mx1, 2));
        const float mn0 = fmaxf(m0r, mx0), mn1 = fmaxf(m1r, mx1);
        const float c0 = __expf(m0r - mn0), c1 = __expf(m1r - mn1);
        float s0 = 0.f, s1s = 0.f;
#pragma unroll
        for (int nt = 0; nt < 8; ++nt) {
            p[nt][0] = __expf(p[nt][0] - mn0);
            p[nt][1] = __expf(p[nt][1] - mn0);
            p[nt][2] = __expf(p[nt][2] - mn1);
            p[nt][3] = __expf(p[nt][3] - mn1);
            s0 += p[nt][0] + p[nt][1];
            s1s += p[nt][2] + p[nt][3];
        }
        s0 += __shfl_xor_sync(0xffffffffu, s0, 1);
        s0 += __shfl_xor_sync(0xffffffffu, s0, 2);
        s1s += __shfl_xor_sync(0xffffffffu, s1s, 1);
        s1s += __shfl_xor_sync(0xffffffffu, s1s, 2);
        l0r = l0r * c0 + s0;
        l1r = l1r * c1 + s1s;
        m0r = mn0; m1r = mn1;
#pragma unroll
        for (int nt = 0; nt < 8; ++nt) {
            o[nt][0] *= c0; o[nt][1] *= c0;
            o[nt][2] *= c1; o[nt][3] *= c1;
        }
        // write P (hi/lo bf16) to smem
#pragma unroll
        for (int nt = 0; nt < 8; ++nt) {
            const int col = nt * 8 + qc;
            *(__nv_bfloat162*)(sm + SO_P  + (iiA * PA + col) * 2) = split_hi2(p[nt][0], p[nt][1]);
            *(__nv_bfloat162*)(sm + SO_PL + (iiA * PA + col) * 2) = split_lo2(p[nt][0], p[nt][1]);
            *(__nv_bfloat162*)(sm + SO_P  + (iiB * PA + col) * 2) = split_hi2(p[nt][2], p[nt][3]);
            *(__nv_bfloat162*)(sm + SO_PL + (iiB * PA + col) * 2) = split_lo2(p[nt][2], p[nt][3]);
        }
        __syncthreads();   // P visible

        // ---- PV: O += P @ V (3-term) ----
#pragma unroll
        for (int ks = 0; ks < 4; ++ks) {
            uint32_t Ap[4], Apl[4], Vb[4][4], Vbl[4][4];
            ldsm4(Ap,  sb + SO_P  + ((w * 16 + a_row) * PA + ks * 16 + a_col) * 2);
            ldsm4(Apl, sb + SO_PL + ((w * 16 + a_row) * PA + ks * 16 + a_col) * 2);
#pragma unroll
            for (int nt2 = 0; nt2 < 4; ++nt2) {
                ldsm4(Vb[nt2],  sb + SO_V  + ((nt2 * 16 + b_row) * PA + ks * 16 + b_col) * 2);
                ldsm4(Vbl[nt2], sb + SO_VL + ((nt2 * 16 + b_row) * PA + ks * 16 + b_col) * 2);
            }
#pragma unroll
            for (int nt = 0; nt < 8; ++nt) {
                mma16816(o[nt], Ap,  &Vb[nt >> 1][(nt & 1) * 2]);
                mma16816(o[nt], Ap,  &Vbl[nt >> 1][(nt & 1) * 2]);
                mma16816(o[nt], Apl, &Vb[nt >> 1][(nt & 1) * 2]);
            }
        }
    }

    // ---- write y (split bf16 directly) ----
    const float iv0 = 1.f / l0r, iv1 = 1.f / l1r;
    const size_t rowA = (size_t)b * T_ + i0 + iiA;
    const size_t rowB = rowA + 8;
#pragma unroll
    for (int nt = 0; nt < 8; ++nt) {
        const int col = h * HD_ + nt * 8 + qc;
        float v0 = o[nt][0] * iv0, v1 = o[nt][1] * iv0;
        float v2 = o[nt][2] * iv1, v3 = o[nt][3] * iv1;
        ((__nv_bfloat162*)g_yh)[(rowA * C_ + col) >> 1] = split_hi2(v0, v1);
        ((__nv_bfloat162*)g_yl)[(rowA * C_ + col) >> 1] = split_lo2(v0, v1);
        ((__nv_bfloat162*)g_yh)[(rowB * C_ + col) >> 1] = split_hi2(v2, v3);
        ((__nv_bfloat162*)g_yl)[(rowB * C_ + col) >> 1] = split_lo2(v2, v3);
    }
}

// ---------------------------------------------------------------------------
// Prep kernels
// ---------------------------------------------------------------------------
__global__ void split_kernel(const float* __restrict__ src,
                             __nv_bfloat16* __restrict__ hi,
                             __nv_bfloat16* __restrict__ lo, int n4)
{
    int i = blockIdx.x * blockDim.x + threadIdx.x;
    if (i >= n4) return;
    float4 v = *(const float4*)(src + (size_t)i * 4);
    ((__nv_bfloat162*)hi)[i * 2 + 0] = split_hi2(v.x, v.y);
    ((__nv_bfloat162*)hi)[i * 2 + 1] = split_hi2(v.z, v.w);
    ((__nv_bfloat162*)lo)[i * 2 + 0] = split_lo2(v.x, v.y);
    ((__nv_bfloat162*)lo)[i * 2 + 1] = split_lo2(v.z, v.w);
}

__global__ void transpose_split_kernel(const float* __restrict__ W,
                                       __nv_bfloat16* __restrict__ th,
                                       __nv_bfloat16* __restrict__ tl, int K, int N)
{
    __shared__ float tile[32][33];
    const int tx = threadIdx.x, ty = threadIdx.y;
    const int n0 = blockIdx.x * 32, k0 = blockIdx.y * 32;
#pragma unroll
    for (int j = 0; j < 4; ++j)
        tile[ty + j * 8][tx] = W[(size_t)(k0 + ty + j * 8) * N + n0 + tx];
    __syncthreads();
#pragma unroll
    for (int j = 0; j < 4; ++j) {
        float v = tile[tx][ty + j * 8];
        __nv_bfloat16 hh = __float2bfloat16(v);
        __nv_bfloat16 ll = __float2bfloat16(v - __bfloat162float(hh));
        size_t o = (size_t)(n0 + ty + j * 8) * K + k0 + tx;
        th[o] = hh; tl[o] = ll;
    }
}

// split qkv into per-head q/k (row) and v (transposed) bf16 hi/lo
__global__ __launch_bounds__(256)
void qkv_split_kernel()
{
    __shared__ float sv[64][65];
    const int tid = threadIdx.x;
    const int bh = blockIdx.y, t0 = blockIdx.x * 64;
    const int b = bh >> 4, h = bh & 15;
    const float* src = g_qkv + ((size_t)(b * T_ + t0)) * C3_ + h * HD_;

#pragma unroll
    for (int u = 0; u < 4; ++u) {
        int idx = u * 256 + tid;
        int r = idx >> 4, c = idx & 15;      // c in float4 units
        float4 q4 = *(const float4*)(src + (size_t)r * C3_ + c * 4);
        float4 k4 = *(const float4*)(src + (size_t)r * C3_ + C_ + c * 4);
        float4 v4 = *(const float4*)(src + (size_t)r * C3_ + 2 * C_ + c * 4);
        size_t oq = (((size_t)bh * T_ + t0 + r) * HD_ + c * 4) >> 1;  // bf162 units
        ((__nv_bfloat162*)g_qh)[oq + 0] = split_hi2(q4.x, q4.y);
        ((__nv_bfloat162*)g_qh)[oq + 1] = split_hi2(q4.z, q4.w);
        ((__nv_bfloat162*)g_ql)[oq + 0] = split_lo2(q4.x, q4.y);
        ((__nv_bfloat162*)g_ql)[oq + 1] = split_lo2(q4.z, q4.w);
        ((__nv_bfloat162*)g_kh)[oq + 0] = split_hi2(k4.x, k4.y);
        ((__nv_bfloat162*)g_kh)[oq + 1] = split_hi2(k4.z, k4.w);
        ((__nv_bfloat162*)g_kl)[oq + 0] = split_lo2(k4.x, k4.y);
        ((__nv_bfloat162*)g_kl)[oq + 1] = split_lo2(k4.z, k4.w);
        sv[r][c * 4 + 0] = v4.x; sv[r][c * 4 + 1] = v4.y;
        sv[r][c * 4 + 2] = v4.z; sv[r][c * 4 + 3] = v4.w;
    }
    __syncthreads();
    // V transpose: 64 d-rows x 4 t-groups = 256 items, exactly one per thread
    {
        int d = tid >> 2, cg = tid & 3;
        size_t ob = (((size_t)bh * HD_ + d) * T_ + t0 + cg * 16) >> 1;  // bf162 units
#pragma unroll
        for (int tt = 0; tt < 16; tt += 2) {
            float v0 = sv[cg * 16 + tt][d], v1 = sv[cg * 16 + tt + 1][d];
            ((__nv_bfloat162*)g_vth)[ob + (tt >> 1)] = split_hi2(v0, v1);
            ((__nv_bfloat162*)g_vtl)[ob + (tt >> 1)] = split_lo2(v0, v1);
        }
    }
}

__global__ void esplit_kernel(const float* __restrict__ rel)
{
    int i = blockIdx.x * blockDim.x + threadIdx.x;   // float4 index
    const int n4 = H_ * T_ * HD_ / 4;
    if (i >= n4) return;
    float4 v = *(const float4*)(rel + (size_t)i * 4);
    ((__nv_bfloat162*)g_eh)[i * 2 + 0] = split_hi2(v.x, v.y);
    ((__nv_bfloat162*)g_eh)[i * 2 + 1] = split_hi2(v.z, v.w);
}

// ---------------------------------------------------------------------------
extern "C" void kernel_launch(void* const* d_in, const int* in_sizes, int n_in,
                              void* d_out, int out_size)
{
    (void)in_sizes; (void)n_in; (void)out_size;
    const float* x      = (const float*)d_in[0];
    const float* W_attn = (const float*)d_in[1];
    const float* b_attn = (const float*)d_in[2];
    const float* W_proj = (const float*)d_in[3];
    const float* b_proj = (const float*)d_in[4];
    const float* rel    = (const float*)d_in[5];
    float* out = (float*)d_out;

    float* qkv = nullptr;
    __nv_bfloat16 *xh, *xl, *yh, *yl, *wah, *wal, *wph, *wpl;
    cudaGetSymbolAddress((void**)&qkv, g_qkv);
    cudaGetSymbolAddress((void**)&xh,  g_xh);
    cudaGetSymbolAddress((void**)&xl,  g_xl);
    cudaGetSymbolAddress((void**)&yh,  g_yh);
    cudaGetSymbolAddress((void**)&yl,  g_yl);
    cudaGetSymbolAddress((void**)&wah, g_wah);
    cudaGetSymbolAddress((void**)&wal, g_wal);
    cudaGetSymbolAddress((void**)&wph, g_wph);
    cudaGetSymbolAddress((void**)&wpl, g_wpl);

    cudaFuncSetAttribute(attn_mma_kernel,
                         cudaFuncAttributeMaxDynamicSharedMemorySize, ATTN_SMEM_BYTES);

    // prep
    {
        int n4 = B_ * T_ * C_ / 4;
        split_kernel<<<(n4 + 255) / 256, 256>>>(x, xh, xl, n4);
        transpose_split_kernel<<<dim3(C3_ / 32, C_ / 32), dim3(32, 8)>>>(W_attn, wah, wal, C_, C3_);
        transpose_split_kernel<<<dim3(C_ / 32, C_ / 32), dim3(32, 8)>>>(W_proj, wph, wpl, C_, C_);
        int ne4 = H_ * T_ * HD_ / 4;
        esplit_kernel<<<(ne4 + 255) / 256, 256>>>(rel);
    }

    // 1) qkv = x @ W_attn + b_attn
    gemm_mma_kernel<<<dim3(C3_ / 128, (B_ * T_) / 128), 256>>>(
        xh, xl, wah, wal, b_attn, qkv, B_ * T_, C3_, C_);

    // 2) per-head split (+ V transpose)
    qkv_split_kernel<<<dim3(T_ / 64, B_ * H_), 256>>>();

    // 3) MMA flash attention -> yh/yl
    attn_mma_kernel<<<dim3(B_ * H_, T_ / 64), 128, ATTN_SMEM_BYTES>>>();

    // 4) out = y @ W_proj + b_proj
    gemm_mma_kernel<<<dim3(C_ / 128, (B_ * T_) / 128), 256>>>(
        yh, yl, wph, wpl, b_proj, out, B_ * T_, C_, C_);
}